// round 10
// baseline (speedup 1.0000x reference)
#include <cuda_runtime.h>
#include <cuda_fp16.h>
#include <mma.h>
#include <cstdint>
#include <cstddef>

using namespace nvcuda;

#define NN   16384
#define DF   256
#define KCAT 512

// ---------------- device-global scratch ----------------
__device__ uint8_t g_ftT8[(size_t)DF * NN];  // features^T e4m3 [256][16384]
__device__ __half  g_cat[(size_t)NN * KCAT]; // [features | neigh] fp16 [16384][512]
__device__ __half  g_w[(size_t)DF * KCAT];   // W fp16 [256][512]

// ---------------- k_main smem (fp8, BK=64) ----------------
// A [2][128][80]B @0 ; B [3][256][80]B @20480 ; srow @81920
constexpr int AST8 = 80;                  // bytes per row (conflict-free: r*20 mod 32 distinct)
constexpr int A_STG8 = 128 * AST8;        // 10240
constexpr int B_STG8 = 256 * AST8;        // 20480
constexpr int OFF_BM8 = 2 * A_STG8;       // 20480
constexpr int OFF_SROW8 = OFF_BM8 + 3 * B_STG8;  // 81920
constexpr int SMEM_MAIN = OFF_SROW8 + 512;       // 82432

// ---------------- k_out smem: 4-stage, BK=32 (fp16, unchanged from R9) ----------------
constexpr int AST = 40;
constexpr int AO_STG = 128 * AST * 2;     // 10240
constexpr int BO_STG = 256 * AST * 2;     // 20480
constexpr int OFF_BO = 4 * AO_STG;        // 40960
constexpr int SST = 68;
constexpr int SMEM_OUT = OFF_BO + 4 * BO_STG + 512;  // 123392

__device__ __forceinline__ uint32_t smem_u32(const void* p) {
    uint32_t a;
    asm("{ .reg .u64 t; cvta.to.shared.u64 t, %1; cvt.u32.u64 %0, t; }" : "=r"(a) : "l"(p));
    return a;
}
__device__ __forceinline__ void cpa16(uint32_t saddr, const void* g) {
    asm volatile("cp.async.cg.shared.global [%0], [%1], 16;" :: "r"(saddr), "l"(g));
}
__device__ __forceinline__ void cpa_commit() { asm volatile("cp.async.commit_group;" ::: "memory"); }
__device__ __forceinline__ void cpa_wait0()  { asm volatile("cp.async.wait_group 0;" ::: "memory"); }
__device__ __forceinline__ void cpa_wait1()  { asm volatile("cp.async.wait_group 1;" ::: "memory"); }
__device__ __forceinline__ void cpa_wait2()  { asm volatile("cp.async.wait_group 2;" ::: "memory"); }

// pack float4 -> 4 e4m3 bytes, LSB..MSB = x,y,z,w  (cvt d,a,b puts b in low byte)
__device__ __forceinline__ uint32_t fp8x4(float4 v) {
    unsigned short lo, hi;
    asm("cvt.rn.satfinite.e4m3x2.f32 %0, %1, %2;" : "=h"(lo) : "f"(v.y), "f"(v.x));
    asm("cvt.rn.satfinite.e4m3x2.f32 %0, %1, %2;" : "=h"(hi) : "f"(v.w), "f"(v.z));
    return (uint32_t)lo | ((uint32_t)hi << 16);
}
__device__ __forceinline__ uint8_t fp8x1(float v) {
    unsigned short lo;
    asm("cvt.rn.satfinite.e4m3x2.f32 %0, %1, %2;" : "=h"(lo) : "f"(v), "f"(v));
    return (uint8_t)(lo & 0xFF);
}

// QMMA: D(16x8,f32) += A(16x32,e4m3 row) * B(32x8,e4m3 col)
__device__ __forceinline__ void mma_fp8(float* d, uint32_t a0, uint32_t a1, uint32_t a2, uint32_t a3,
                                        uint32_t b0, uint32_t b1) {
    asm volatile(
        "mma.sync.aligned.m16n8k32.row.col.f32.e4m3.e4m3.f32 "
        "{%0,%1,%2,%3}, {%4,%5,%6,%7}, {%8,%9}, {%0,%1,%2,%3};"
        : "+f"(d[0]), "+f"(d[1]), "+f"(d[2]), "+f"(d[3])
        : "r"(a0), "r"(a1), "r"(a2), "r"(a3), "r"(b0), "r"(b1));
}

// ---------------- prep: features -> g_ftT8 (transposed e4m3) + g_cat[:, :256] fp16 ----------------
__global__ void __launch_bounds__(256) k_prep(const float* __restrict__ f) {
    __shared__ float t[32][33];
    int n0 = blockIdx.x * 32, d0 = blockIdx.y * 32;
    int tx = threadIdx.x, ty = threadIdx.y;
    #pragma unroll
    for (int i = ty; i < 32; i += 8) {
        float v = f[(size_t)(n0 + i) * DF + d0 + tx];
        t[i][tx] = v;
        g_cat[(size_t)(n0 + i) * KCAT + d0 + tx] = __float2half(v);
    }
    __syncthreads();
    #pragma unroll
    for (int i = ty; i < 32; i += 8)
        g_ftT8[(size_t)(d0 + i) * NN + n0 + tx] = fp8x1(t[tx][i]);
}

__global__ void __launch_bounds__(256) k_wconv(const float* __restrict__ W, int base) {
    int i = base + blockIdx.x * 256 + threadIdx.x;
    g_w[i] = __float2half(W[i]);
}

// ================= k_main: fp8 QMMA, 512 threads, 16 warps (4x4), warp tile 32x64 =================
__global__ void __launch_bounds__(512, 1) k_main(const float* __restrict__ adj) {
    extern __shared__ char sm[];
    char*  Abuf = sm;                          // [2][128][80] e4m3
    char*  Bbuf = sm + OFF_BM8;                // [3][256][80] e4m3
    float* srow = (float*)(sm + OFF_SROW8);    // [128]

    const int tid = threadIdx.x;
    const int lane = tid & 31;
    const int wid = tid >> 5;
    const int wm = wid >> 2, wn = wid & 3;     // 4x4 warps, 32x64 warp tiles
    const int m0 = blockIdx.x * 128;
    const uint32_t b_u32 = smem_u32(Bbuf);

    float acc[2][8][4];                        // [mt][nt][frag]
    #pragma unroll
    for (int mt = 0; mt < 2; mt++)
        #pragma unroll
        for (int nt = 0; nt < 8; nt++)
            #pragma unroll
            for (int q = 0; q < 4; q++) acc[mt][nt][q] = 0.0f;

    float rowacc[4] = {0.f, 0.f, 0.f, 0.f};
    float4 va[4];

    auto ldgA = [&](int it) {
        int k0 = it * 64;
        #pragma unroll
        for (int j = 0; j < 4; j++) {
            int idx = tid + j * 512;
            int row = idx >> 4, c4 = idx & 15;      // 16 x float4 per 64-col row
            va[j] = *(const float4*)(adj + (size_t)(m0 + row) * NN + k0 + c4 * 4);
        }
    };
    auto stsA = [&](int buf) {
        char* At = Abuf + buf * A_STG8;
        #pragma unroll
        for (int j = 0; j < 4; j++) {
            int idx = tid + j * 512;
            int row = idx >> 4, c4 = idx & 15;
            float4 v = va[j];
            rowacc[j] += (v.x + v.y) + (v.z + v.w);
            *(uint32_t*)(At + row * AST8 + c4 * 4) = fp8x4(v);
        }
    };
    auto cpaB = [&](int buf, int it) {
        int k0 = it * 64;
        uint32_t b0 = b_u32 + buf * B_STG8;
        #pragma unroll
        for (int j = 0; j < 2; j++) {               // 256 rows x 4 x 16B = 1024 chunks
            int idx = tid + j * 512;
            int row = idx >> 2, c16 = idx & 3;
            cpa16(b0 + row * AST8 + c16 * 16, g_ftT8 + (size_t)row * NN + k0 + c16 * 16);
        }
    };

    // ---- prologue ----
    ldgA(0);
    stsA(0);
    ldgA(1);
    cpaB(0, 0); cpa_commit();
    cpaB(1, 1); cpa_commit();

    constexpr int NK = NN / 64;  // 256
    int bs = 0, bs2 = 2;

    const int arow = wm * 32 + (lane >> 2);
    const int bq = (lane & 3) * 4;

    #pragma unroll 1
    for (int it = 0; it < NK; ++it) {
        int cur = it & 1;
        cpa_wait1();
        __syncthreads();

        if (it + 1 < NK) stsA(cur ^ 1);
        if (it + 2 < NK) {
            ldgA(it + 2);
            cpaB(bs2, it + 2);
        }
        cpa_commit();

        const char* At = Abuf + cur * A_STG8;
        const char* Bt = Bbuf + bs * B_STG8;
        #pragma unroll
        for (int kt = 0; kt < 2; ++kt) {
            int kb = kt * 32 + bq;
            uint32_t af[2][4];
            #pragma unroll
            for (int mt = 0; mt < 2; mt++) {
                const char* ab = At + (arow + mt * 16) * AST8 + kb;
                af[mt][0] = *(const uint32_t*)(ab);
                af[mt][1] = *(const uint32_t*)(ab + 8 * AST8);
                af[mt][2] = *(const uint32_t*)(ab + 16);
                af[mt][3] = *(const uint32_t*)(ab + 8 * AST8 + 16);
            }
            #pragma unroll
            for (int nt = 0; nt < 8; nt++) {
                const char* bb = Bt + (wn * 64 + nt * 8 + (lane >> 2)) * AST8 + kb;
                uint32_t b0 = *(const uint32_t*)(bb);
                uint32_t b1 = *(const uint32_t*)(bb + 16);
                #pragma unroll
                for (int mt = 0; mt < 2; mt++)
                    mma_fp8(acc[mt][nt], af[mt][0], af[mt][1], af[mt][2], af[mt][3], b0, b1);
            }
        }
        bs = (bs == 2) ? 0 : bs + 1;
        bs2 = (bs2 == 2) ? 0 : bs2 + 1;
    }
    cpa_wait0();

    // exact fp32 rowsum -> 1/(deg+1); 16 lanes share a row
    #pragma unroll
    for (int j = 0; j < 4; j++) {
        float s = rowacc[j];
        s += __shfl_xor_sync(0xFFFFFFFFu, s, 1);
        s += __shfl_xor_sync(0xFFFFFFFFu, s, 2);
        s += __shfl_xor_sync(0xFFFFFFFFu, s, 4);
        s += __shfl_xor_sync(0xFFFFFFFFu, s, 8);
        int row = (tid + j * 512) >> 4;
        if ((lane & 15) == 0) srow[row] = 1.0f / (s + 1.0f);
    }
    __syncthreads();

    // epilogue: registers -> g_cat directly (half2 stores)
    #pragma unroll
    for (int mt = 0; mt < 2; mt++) {
        int r0 = wm * 32 + mt * 16 + (lane >> 2);
        float i0 = srow[r0], i1 = srow[r0 + 8];
        #pragma unroll
        for (int nt = 0; nt < 8; nt++) {
            int c = wn * 64 + nt * 8 + (lane & 3) * 2;
            __half2 h0 = __floats2half2_rn(acc[mt][nt][0] * i0, acc[mt][nt][1] * i0);
            __half2 h1 = __floats2half2_rn(acc[mt][nt][2] * i1, acc[mt][nt][3] * i1);
            *(__half2*)(g_cat + (size_t)(m0 + r0) * KCAT + 256 + c) = h0;
            *(__half2*)(g_cat + (size_t)(m0 + r0 + 8) * KCAT + 256 + c) = h1;
        }
    }
}

// ================= k_out: fp16, 4-stage pipeline (unchanged from R9) =================
__global__ void __launch_bounds__(512, 1) k_out(float* __restrict__ out) {
    extern __shared__ char sm[];
    __half* Abuf = (__half*)sm;                // [4][128][40]
    __half* Bbuf = (__half*)(sm + OFF_BO);     // [4][256][40]
    float*  stage = (float*)sm;                // epilogue reuse [128][68]

    const int tid = threadIdx.x;
    const int wid = tid >> 5;
    const int wm = wid >> 2, wn = wid & 3;
    const int m0 = blockIdx.x * 128;
    const uint32_t a_u32 = smem_u32(Abuf);
    const uint32_t b_u32 = smem_u32(Bbuf);

    wmma::fragment<wmma::accumulator, 16, 16, 16, float> acc[2][4];
    #pragma unroll
    for (int mi = 0; mi < 2; mi++)
        #pragma unroll
        for (int ni = 0; ni < 4; ni++)
            wmma::fill_fragment(acc[mi][ni], 0.0f);

    auto loadTile = [&](int slot, int it) {
        int k0 = it * 32;
        uint32_t a0 = a_u32 + slot * AO_STG;
        uint32_t b0 = b_u32 + slot * BO_STG;
        {
            int row = tid >> 2, c8 = tid & 3;
            cpa16(a0 + (row * AST + c8 * 8) * 2, g_cat + (size_t)(m0 + row) * KCAT + k0 + c8 * 8);
        }
        #pragma unroll
        for (int j = 0; j < 2; j++) {
            int idx = tid + j * 512;
            int row = idx >> 2, c8 = idx & 3;
            cpa16(b0 + (row * AST + c8 * 8) * 2, g_w + (size_t)row * KCAT + k0 + c8 * 8);
        }
    };

    loadTile(0, 0); cpa_commit();
    loadTile(1, 1); cpa_commit();
    loadTile(2, 2); cpa_commit();

    constexpr int NK = KCAT / 32;  // 16
    #pragma unroll 1
    for (int it = 0; it < NK; ++it) {
        int cur = it & 3;
        cpa_wait2();
        __syncthreads();

        if (it + 3 < NK) { loadTile((it + 3) & 3, it + 3); cpa_commit(); }

        const __half* At = Abuf + cur * 128 * AST;
        const __half* Bt = Bbuf + cur * 256 * AST;
        #pragma unroll
        for (int ks = 0; ks < 2; ++ks) {
            wmma::fragment<wmma::matrix_a, 16, 16, 16, __half, wmma::row_major> af[2];
            #pragma unroll
            for (int mi = 0; mi < 2; mi++)
                wmma::load_matrix_sync(af[mi], At + (wm * 32 + mi * 16) * AST + ks * 16, AST);
            #pragma unroll
            for (int ni = 0; ni < 4; ni++) {
                wmma::fragment<wmma::matrix_b, 16, 16, 16, __half, wmma::col_major> bf;
                wmma::load_matrix_sync(bf, Bt + (wn * 64 + ni * 16) * AST + ks * 16, AST);
                #pragma unroll
                for (int mi = 0; mi < 2; mi++)
                    wmma::mma_sync(acc[mi][ni], af[mi], bf, acc[mi][ni]);
            }
        }
    }
    cpa_wait0();
    __syncthreads();

    #pragma unroll 1
    for (int p = 0; p < 4; p++) {
        if (wn == p) {
            #pragma unroll
            for (int mi = 0; mi < 2; mi++)
                #pragma unroll
                for (int ni = 0; ni < 4; ni++)
                    wmma::store_matrix_sync(stage + (wm * 32 + mi * 16) * SST + ni * 16,
                                            acc[mi][ni], SST, wmma::mem_row_major);
        }
        __syncthreads();
        #pragma unroll
        for (int j = 0; j < 16; j++) {
            int idx = tid + j * 512;
            int r = idx >> 6, c = idx & 63;
            out[(size_t)(m0 + r) * DF + p * 64 + c] = stage[r * SST + c];
        }
        __syncthreads();
    }
}

// ---------------- launch ----------------
extern "C" void kernel_launch(void* const* d_in, const int* in_sizes, int n_in,
                              void* d_out, int out_size) {
    const float* features = nullptr;
    const float* adj = nullptr;
    const float* W = nullptr;
    for (int i = 0; i < n_in; i++) {
        if (in_sizes[i] == NN * NN) adj = (const float*)d_in[i];
        else if (in_sizes[i] == NN * DF) features = (const float*)d_in[i];
        else if (in_sizes[i] == DF * KCAT) W = (const float*)d_in[i];
    }
    float* out = (float*)d_out;

    cudaFuncSetAttribute(k_main, cudaFuncAttributeMaxDynamicSharedMemorySize, SMEM_MAIN);
    cudaFuncSetAttribute(k_out,  cudaFuncAttributeMaxDynamicSharedMemorySize, SMEM_OUT);

    // k_main stays at launch index 3 (ncu capture slot)
    k_prep<<<dim3(NN / 32, DF / 32), dim3(32, 8)>>>(features);
    k_wconv<<<(DF * KCAT / 2) / 256, 256>>>(W, 0);
    k_wconv<<<(DF * KCAT / 2) / 256, 256>>>(W, DF * KCAT / 2);
    k_main<<<NN / 128, 512, SMEM_MAIN>>>(adj);
    k_out<<<NN / 128, 512, SMEM_OUT>>>(out);
}